// round 3
// baseline (speedup 1.0000x reference)
#include <cuda_runtime.h>

// ---------------------------------------------------------------------------
// MultiHeadAttention: x[B,S,D] -> MHA -> out[B,S,D]
// B=2, S=2048, D=1024, H=16, d=64.  All fp32 (baseline, FFMA-bound).
// Pipeline: 3x SGEMM (QKV proj, head-split epilogue) -> flash attention
//           -> 1x SGEMM (output proj + bias) into d_out.
// ---------------------------------------------------------------------------

constexpr int S_LEN = 2048;
constexpr int DM    = 1024;
constexpr int NH    = 16;
constexpr int HD    = 64;
constexpr int BATCH = 2;
constexpr int MROWS = BATCH * S_LEN;   // 4096

// Scratch (allocation-free rule: __device__ globals)
__device__ float g_q  [(size_t)BATCH * NH * S_LEN * HD];
__device__ float g_k  [(size_t)BATCH * NH * S_LEN * HD];
__device__ float g_v  [(size_t)BATCH * NH * S_LEN * HD];
__device__ float g_ctx[(size_t)MROWS * DM];

// ---------------------------------------------------------------------------
// SGEMM: C[M=4096, N=1024] = A[M,K=1024] @ W[K,N] + bias[N]
// 128x128 block tile, BK=8, 256 threads, 8x8 per-thread tile.
// MODE 0: plain row-major write (out projection -> d_out)
// MODE 1: head-split write into [B,H,S,d] layout (QKV projections)
// ---------------------------------------------------------------------------
template<int MODE>
__global__ void __launch_bounds__(256)
gemm_kernel(const float* __restrict__ A, const float* __restrict__ W,
            const float* __restrict__ bias, float* __restrict__ out)
{
    constexpr int K = DM;
    constexpr int N = DM;

    __shared__ float As[8][128];   // transposed A tile: As[k][m]
    __shared__ float Bs[8][128];   // Bs[k][n]

    const int tid  = threadIdx.x;
    const int tx   = tid & 15;     // 0..15 (col group)
    const int ty   = tid >> 4;     // 0..15 (row group)
    const int brow = blockIdx.y * 128;
    const int bcol = blockIdx.x * 128;

    float acc[8][8];
#pragma unroll
    for (int i = 0; i < 8; i++)
#pragma unroll
        for (int j = 0; j < 8; j++) acc[i][j] = 0.f;

    // global-load assignments
    const int a_row = tid >> 1;          // 0..127
    const int a_col = (tid & 1) * 4;     // 0 or 4
    const int b_row = tid >> 5;          // 0..7
    const int b_col = (tid & 31) * 4;    // 0..124

    const float* Ap = A + (size_t)(brow + a_row) * K + a_col;
    const float* Wp = W + (size_t)b_row * N + bcol + b_col;

    for (int k0 = 0; k0 < K; k0 += 8) {
        float4 av = *(const float4*)(Ap + k0);
        As[a_col + 0][a_row] = av.x;
        As[a_col + 1][a_row] = av.y;
        As[a_col + 2][a_row] = av.z;
        As[a_col + 3][a_row] = av.w;
        *(float4*)&Bs[b_row][b_col] = *(const float4*)(Wp + (size_t)k0 * N);
        __syncthreads();

#pragma unroll
        for (int k = 0; k < 8; k++) {
            float ar[8], br[8];
#pragma unroll
            for (int i = 0; i < 8; i++) ar[i] = As[k][ty * 8 + i];
#pragma unroll
            for (int j = 0; j < 8; j++) br[j] = Bs[k][tx + 16 * j];
#pragma unroll
            for (int i = 0; i < 8; i++)
#pragma unroll
                for (int j = 0; j < 8; j++)
                    acc[i][j] += ar[i] * br[j];
        }
        __syncthreads();
    }

#pragma unroll
    for (int i = 0; i < 8; i++) {
        const int m = brow + ty * 8 + i;
#pragma unroll
        for (int j = 0; j < 8; j++) {
            const int n = bcol + tx + 16 * j;
            const float v = acc[i][j] + bias[n];
            if (MODE == 0) {
                out[(size_t)m * N + n] = v;
            } else {
                // m = b*S + s ; n = h*HD + dd  ->  [b,h,s,dd]
                const int b  = m >> 11;         // /2048
                const int s  = m & 2047;
                const int h  = n >> 6;          // /64
                const int dd = n & 63;
                out[(((size_t)(b * NH + h) * S_LEN) + s) * HD + dd] = v;
            }
        }
    }
}

// ---------------------------------------------------------------------------
// Flash attention (fp32, online softmax).
// Block = (q-tile of 64 rows, head, batch). 256 threads (16x16).
// KV tiles of 32. Per-thread 4x4 output tile over [64 q-rows x 64 depth].
// ---------------------------------------------------------------------------
__global__ void __launch_bounds__(256)
attn_kernel(const float* __restrict__ Q, const float* __restrict__ Km,
            const float* __restrict__ Vm, float* __restrict__ ctx)
{
    __shared__ float Qs[64][68];
    __shared__ float Ks[32][68];
    __shared__ float Vs[32][68];
    __shared__ float Ps[64][36];          // scores -> probs (in place)
    __shared__ float m_s[64], l_s[64], scale_s[64];

    const int tid = threadIdx.x;
    const int tx  = tid & 15;
    const int ty  = tid >> 4;
    const int qt0 = blockIdx.x * 64;
    const int h   = blockIdx.y;
    const int b   = blockIdx.z;
    const size_t head_base = (size_t)(b * NH + h) * S_LEN * HD;

    // load Q tile [64][64]
    {
        const int r = tid >> 4;           // 0..15
        const int c = (tid & 15) * 4;     // 0..60
#pragma unroll
        for (int p = 0; p < 4; p++) {
            const int row = r + 16 * p;
            *(float4*)&Qs[row][c] =
                *(const float4*)&Q[head_base + (size_t)(qt0 + row) * HD + c];
        }
    }
    if (tid < 64) { m_s[tid] = -1e30f; l_s[tid] = 0.f; }

    float acc[4][4];
#pragma unroll
    for (int i = 0; i < 4; i++)
#pragma unroll
        for (int j = 0; j < 4; j++) acc[i][j] = 0.f;
    __syncthreads();

    for (int kt0 = 0; kt0 < S_LEN; kt0 += 32) {
        // load K,V tiles [32][64]
        {
            const int r = tid >> 4;
            const int c = (tid & 15) * 4;
#pragma unroll
            for (int p = 0; p < 2; p++) {
                const int row = r + 16 * p;
                const size_t g = head_base + (size_t)(kt0 + row) * HD + c;
                *(float4*)&Ks[row][c] = *(const float4*)&Km[g];
                *(float4*)&Vs[row][c] = *(const float4*)&Vm[g];
            }
        }
        __syncthreads();

        // ---- scores: S[64 x 32] = Q @ K^T * (1/8) ----
        float s[4][2];
#pragma unroll
        for (int i = 0; i < 4; i++)
#pragma unroll
            for (int j = 0; j < 2; j++) s[i][j] = 0.f;

#pragma unroll
        for (int kk = 0; kk < 64; kk += 4) {
            float4 qv[4], kv[2];
#pragma unroll
            for (int i = 0; i < 4; i++) qv[i] = *(const float4*)&Qs[ty + 16 * i][kk];
#pragma unroll
            for (int j = 0; j < 2; j++) kv[j] = *(const float4*)&Ks[tx + 16 * j][kk];
#pragma unroll
            for (int i = 0; i < 4; i++)
#pragma unroll
                for (int j = 0; j < 2; j++) {
                    s[i][j] += qv[i].x * kv[j].x + qv[i].y * kv[j].y
                             + qv[i].z * kv[j].z + qv[i].w * kv[j].w;
                }
        }
#pragma unroll
        for (int i = 0; i < 4; i++)
#pragma unroll
            for (int j = 0; j < 2; j++)
                Ps[ty + 16 * i][tx + 16 * j] = s[i][j] * 0.125f;
        __syncthreads();

        // ---- online softmax over the 32-wide tile (4 threads / row) ----
        {
            const int row = tid >> 2;     // 0..63
            const int q   = tid & 3;      // 0..3, lanes 4r..4r+3 share a row
            float mx = -1e30f;
#pragma unroll
            for (int c = 0; c < 8; c++) mx = fmaxf(mx, Ps[row][q * 8 + c]);
            mx = fmaxf(mx, __shfl_xor_sync(0xffffffffu, mx, 1));
            mx = fmaxf(mx, __shfl_xor_sync(0xffffffffu, mx, 2));
            const float m_old = m_s[row];
            const float m_new = fmaxf(m_old, mx);
            float sum = 0.f;
#pragma unroll
            for (int c = 0; c < 8; c++) {
                const float p = __expf(Ps[row][q * 8 + c] - m_new);
                Ps[row][q * 8 + c] = p;
                sum += p;
            }
            sum += __shfl_xor_sync(0xffffffffu, sum, 1);
            sum += __shfl_xor_sync(0xffffffffu, sum, 2);
            if (q == 0) {
                const float sc = __expf(m_old - m_new);
                l_s[row]     = l_s[row] * sc + sum;
                m_s[row]     = m_new;
                scale_s[row] = sc;
            }
        }
        __syncthreads();

        // ---- O update: rescale then acc += P @ V ----
#pragma unroll
        for (int i = 0; i < 4; i++) {
            const float sc = scale_s[ty + 16 * i];
#pragma unroll
            for (int j = 0; j < 4; j++) acc[i][j] *= sc;
        }
#pragma unroll
        for (int kk = 0; kk < 32; kk += 4) {
            float4 pv[4];
#pragma unroll
            for (int i = 0; i < 4; i++) pv[i] = *(const float4*)&Ps[ty + 16 * i][kk];
#pragma unroll
            for (int m = 0; m < 4; m++) {
                float vv[4];
#pragma unroll
                for (int j = 0; j < 4; j++) vv[j] = Vs[kk + m][tx + 16 * j];
#pragma unroll
                for (int i = 0; i < 4; i++) {
                    const float p = (m == 0) ? pv[i].x : (m == 1) ? pv[i].y
                                  : (m == 2) ? pv[i].z : pv[i].w;
#pragma unroll
                    for (int j = 0; j < 4; j++)
                        acc[i][j] += p * vv[j];
                }
            }
        }
        __syncthreads();   // before next tile overwrites Ks/Vs/Ps
    }

    // ---- finalize: /l and write concat layout [B,S,H*d] ----
#pragma unroll
    for (int i = 0; i < 4; i++) {
        const int row = ty + 16 * i;
        const float inv = 1.f / l_s[row];
        const int sglob = qt0 + row;
#pragma unroll
        for (int j = 0; j < 4; j++) {
            const int c = tx + 16 * j;
            ctx[((size_t)(b * S_LEN) + sglob) * DM + h * HD + c] = acc[i][j] * inv;
        }
    }
}

// ---------------------------------------------------------------------------
extern "C" void kernel_launch(void* const* d_in, const int* in_sizes, int n_in,
                              void* d_out, int out_size)
{
    const float* x  = (const float*)d_in[0];
    const float* wq = (const float*)d_in[1];
    const float* bq = (const float*)d_in[2];
    const float* wk = (const float*)d_in[3];
    const float* bk = (const float*)d_in[4];
    const float* wv = (const float*)d_in[5];
    const float* bv = (const float*)d_in[6];
    const float* wo = (const float*)d_in[7];
    const float* bo = (const float*)d_in[8];
    float* out = (float*)d_out;

    float *q = nullptr, *k = nullptr, *v = nullptr, *ctx = nullptr;
    cudaGetSymbolAddress((void**)&q,   g_q);
    cudaGetSymbolAddress((void**)&k,   g_k);
    cudaGetSymbolAddress((void**)&v,   g_v);
    cudaGetSymbolAddress((void**)&ctx, g_ctx);

    dim3 gg(DM / 128, MROWS / 128);      // (8, 32)
    gemm_kernel<1><<<gg, 256>>>(x, wq, bq, q);
    gemm_kernel<1><<<gg, 256>>>(x, wk, bk, k);
    gemm_kernel<1><<<gg, 256>>>(x, wv, bv, v);

    dim3 ga(S_LEN / 64, NH, BATCH);      // (32, 16, 2)
    attn_kernel<<<ga, 256>>>(q, k, v, ctx);

    gemm_kernel<0><<<gg, 256>>>(ctx, wo, bo, out);
}

// round 4
// speedup vs baseline: 2.7853x; 2.7853x over previous
#include <cuda_runtime.h>
#include <cstdint>

// ---------------------------------------------------------------------------
// MultiHeadAttention, tf32 tensor-core version.
// B=2, S=2048, D=1024, H=16, d=64.
// 4x GEMM (tf32 mma.sync, 128x128 tile) + flash attention (tf32 mma.sync).
// ---------------------------------------------------------------------------

constexpr int S_LEN = 2048;
constexpr int DM    = 1024;
constexpr int NH    = 16;
constexpr int HD    = 64;
constexpr int BATCH = 2;
constexpr int MROWS = BATCH * S_LEN;   // 4096

__device__ float g_q  [(size_t)BATCH * NH * S_LEN * HD];
__device__ float g_k  [(size_t)BATCH * NH * S_LEN * HD];
__device__ float g_v  [(size_t)BATCH * NH * S_LEN * HD];
__device__ float g_ctx[(size_t)MROWS * DM];

__device__ __forceinline__ uint32_t f2tf32(float x) {
    uint32_t u;
    asm("cvt.rna.tf32.f32 %0, %1;" : "=r"(u) : "f"(x));
    return u;
}

__device__ __forceinline__ void mma_tf32(float* c, const uint32_t* a, const uint32_t* b) {
    asm volatile(
        "mma.sync.aligned.m16n8k8.row.col.f32.tf32.tf32.f32 "
        "{%0,%1,%2,%3}, {%4,%5,%6,%7}, {%8,%9}, {%0,%1,%2,%3};"
        : "+f"(c[0]), "+f"(c[1]), "+f"(c[2]), "+f"(c[3])
        : "r"(a[0]), "r"(a[1]), "r"(a[2]), "r"(a[3]), "r"(b[0]), "r"(b[1]));
}

// ---------------------------------------------------------------------------
// GEMM: C[4096,1024] = A @ W + bias.  tf32 MMA, 128x128 block, 8 warps,
// each warp 64x32, K-chunk 16, double-buffered smem.
// MODE 0: row-major out.  MODE 1: head-split [B,H,S,d] out.
// ---------------------------------------------------------------------------
template<int MODE>
__global__ void __launch_bounds__(256)
gemm_tf32_kernel(const float* __restrict__ A, const float* __restrict__ W,
                 const float* __restrict__ bias, float* __restrict__ out)
{
    constexpr int K = DM, N = DM;
    __shared__ uint32_t As[2][128][20];    // [m][k], stride 20 -> frag banks 4g+tg
    __shared__ uint32_t Bs[2][16][136];    // [k][n], stride 136 -> frag banks 8tg+g

    const int tid  = threadIdx.x;
    const int warp = tid >> 5, lane = tid & 31;
    const int g    = lane >> 2, tg = lane & 3;
    const int wr   = warp >> 2;            // 0..1 -> row base wr*64
    const int wc   = warp & 3;             // 0..3 -> col base wc*32
    const int brow = blockIdx.y * 128;
    const int bcol = blockIdx.x * 128;

    // global load assignments
    const int a_row = tid >> 1;            // 0..127
    const int a_k   = (tid & 1) * 8;       // 0 or 8
    const int b_row = tid >> 4;            // 0..15
    const int b_col = (tid & 15) * 8;      // 0..120

    const float* Ap = A + (size_t)(brow + a_row) * K + a_k;
    const float* Wp = W + (size_t)b_row * N + bcol + b_col;

    float acc[4][4][4];
#pragma unroll
    for (int mt = 0; mt < 4; mt++)
#pragma unroll
        for (int nt = 0; nt < 4; nt++)
#pragma unroll
            for (int i = 0; i < 4; i++) acc[mt][nt][i] = 0.f;

    // prologue: load chunk 0 into buffer 0
    {
        float4 va0 = *(const float4*)(Ap + 0);
        float4 va1 = *(const float4*)(Ap + 4);
        float4 vb0 = *(const float4*)(Wp + 0);
        float4 vb1 = *(const float4*)(Wp + 4);
        uint32_t* as = &As[0][a_row][a_k];
        as[0]=f2tf32(va0.x); as[1]=f2tf32(va0.y); as[2]=f2tf32(va0.z); as[3]=f2tf32(va0.w);
        as[4]=f2tf32(va1.x); as[5]=f2tf32(va1.y); as[6]=f2tf32(va1.z); as[7]=f2tf32(va1.w);
        uint32_t* bs = &Bs[0][b_row][b_col];
        bs[0]=f2tf32(vb0.x); bs[1]=f2tf32(vb0.y); bs[2]=f2tf32(vb0.z); bs[3]=f2tf32(vb0.w);
        bs[4]=f2tf32(vb1.x); bs[5]=f2tf32(vb1.y); bs[6]=f2tf32(vb1.z); bs[7]=f2tf32(vb1.w);
    }
    __syncthreads();

    constexpr int NCHUNK = K / 16;         // 64
    for (int kt = 0; kt < NCHUNK; kt++) {
        const int buf = kt & 1;
        float4 va0, va1, vb0, vb1;
        const bool more = (kt + 1 < NCHUNK);
        if (more) {
            const float* ap = Ap + (kt + 1) * 16;
            const float* wp = Wp + (size_t)(kt + 1) * 16 * N;
            va0 = *(const float4*)(ap + 0);
            va1 = *(const float4*)(ap + 4);
            vb0 = *(const float4*)(wp + 0);
            vb1 = *(const float4*)(wp + 4);
        }

#pragma unroll
        for (int ks = 0; ks < 2; ks++) {
            const int k0 = ks * 8;
            uint32_t a[4][4], b[4][2];
#pragma unroll
            for (int mt = 0; mt < 4; mt++) {
                const int r = wr * 64 + mt * 16 + g;
                a[mt][0] = As[buf][r    ][k0 + tg];
                a[mt][1] = As[buf][r + 8][k0 + tg];
                a[mt][2] = As[buf][r    ][k0 + tg + 4];
                a[mt][3] = As[buf][r + 8][k0 + tg + 4];
            }
#pragma unroll
            for (int nt = 0; nt < 4; nt++) {
                const int c = wc * 32 + nt * 8 + g;
                b[nt][0] = Bs[buf][k0 + tg    ][c];
                b[nt][1] = Bs[buf][k0 + tg + 4][c];
            }
#pragma unroll
            for (int mt = 0; mt < 4; mt++)
#pragma unroll
                for (int nt = 0; nt < 4; nt++)
                    mma_tf32(acc[mt][nt], a[mt], b[nt]);
        }

        if (more) {
            const int nb = buf ^ 1;
            uint32_t* as = &As[nb][a_row][a_k];
            as[0]=f2tf32(va0.x); as[1]=f2tf32(va0.y); as[2]=f2tf32(va0.z); as[3]=f2tf32(va0.w);
            as[4]=f2tf32(va1.x); as[5]=f2tf32(va1.y); as[6]=f2tf32(va1.z); as[7]=f2tf32(va1.w);
            uint32_t* bs = &Bs[nb][b_row][b_col];
            bs[0]=f2tf32(vb0.x); bs[1]=f2tf32(vb0.y); bs[2]=f2tf32(vb0.z); bs[3]=f2tf32(vb0.w);
            bs[4]=f2tf32(vb1.x); bs[5]=f2tf32(vb1.y); bs[6]=f2tf32(vb1.z); bs[7]=f2tf32(vb1.w);
        }
        __syncthreads();
    }

    // epilogue
#pragma unroll
    for (int mt = 0; mt < 4; mt++) {
#pragma unroll
        for (int nt = 0; nt < 4; nt++) {
#pragma unroll
            for (int half = 0; half < 2; half++) {
                const int m = brow + wr * 64 + mt * 16 + g + half * 8;
#pragma unroll
                for (int e = 0; e < 2; e++) {
                    const int n = bcol + wc * 32 + nt * 8 + 2 * tg + e;
                    const float v = acc[mt][nt][half * 2 + e] + bias[n];
                    if (MODE == 0) {
                        out[(size_t)m * N + n] = v;
                    } else {
                        const int bb = m >> 11, s = m & 2047;
                        const int h  = n >> 6,  dd = n & 63;
                        out[(((size_t)(bb * NH + h) * S_LEN) + s) * HD + dd] = v;
                    }
                }
            }
        }
    }
}

// ---------------------------------------------------------------------------
// Flash attention, tf32 MMA.  Block = 64 q-rows x head x batch, 8 warps.
// Warp grid 4x2: wr = rows (16 each), wc = cols (32 each of kv / of d).
// Q held in registers as A-fragments.  KV tile = 64.  P reuses K's smem.
// ---------------------------------------------------------------------------
__global__ void __launch_bounds__(256)
attn_tf32_kernel(const float* __restrict__ Q, const float* __restrict__ Km,
                 const float* __restrict__ Vm, float* __restrict__ ctx)
{
    __shared__ uint32_t KPs[64][68];   // K tile [kv][d] -> then P tile [q][kv]
    __shared__ uint32_t Vs[64][72];    // V tile [kv][d]
    __shared__ float red_max[2][64];
    __shared__ float red_sum[2][64];

    const int tid  = threadIdx.x;
    const int warp = tid >> 5, lane = tid & 31;
    const int g    = lane >> 2, tg = lane & 3;
    const int wr   = warp >> 1;        // 0..3
    const int wc   = warp & 1;         // 0..1
    const int qt0  = blockIdx.x * 64;
    const int h    = blockIdx.y;
    const int b    = blockIdx.z;
    const size_t head_base = (size_t)(b * NH + h) * S_LEN * HD;

    // Q A-fragments in registers: rows wr*16 + {g, g+8}, all 64 k (8 steps)
    uint32_t qa[8][4];
    {
        const float* q0 = Q + head_base + (size_t)(qt0 + wr * 16 + g) * HD;
        const float* q1 = q0 + 8 * HD;
#pragma unroll
        for (int ks = 0; ks < 8; ks++) {
            qa[ks][0] = f2tf32(q0[ks * 8 + tg]);
            qa[ks][1] = f2tf32(q1[ks * 8 + tg]);
            qa[ks][2] = f2tf32(q0[ks * 8 + tg + 4]);
            qa[ks][3] = f2tf32(q1[ks * 8 + tg + 4]);
        }
    }

    const int r0 = wr * 16 + g;        // local q row (thread's first row)
    const int r1 = r0 + 8;
    float m_reg[2] = {-1e30f, -1e30f};
    float l_reg[2] = {0.f, 0.f};
    float oa[4][4];
#pragma unroll
    for (int nt = 0; nt < 4; nt++)
#pragma unroll
        for (int i = 0; i < 4; i++) oa[nt][i] = 0.f;

    // gmem->smem load mapping: 16 floats/thread as 4x float4
    const int ld_row = tid >> 4;       // 0..15 (+16 per iter)
    const int ld_col = (tid & 15) * 4; // 0..60

    for (int kt0 = 0; kt0 < S_LEN; kt0 += 64) {
#pragma unroll
        for (int it = 0; it < 4; it++) {
            const int row = ld_row + it * 16;
            const size_t gaddr = head_base + (size_t)(kt0 + row) * HD + ld_col;
            float4 kv4 = *(const float4*)&Km[gaddr];
            float4 vv4 = *(const float4*)&Vm[gaddr];
            uint32_t* kp = &KPs[row][ld_col];
            kp[0]=f2tf32(kv4.x); kp[1]=f2tf32(kv4.y); kp[2]=f2tf32(kv4.z); kp[3]=f2tf32(kv4.w);
            uint32_t* vp = &Vs[row][ld_col];
            vp[0]=f2tf32(vv4.x); vp[1]=f2tf32(vv4.y); vp[2]=f2tf32(vv4.z); vp[3]=f2tf32(vv4.w);
        }
        __syncthreads();

        // ---- S = Q @ K^T (warp: rows wr*16+16, cols wc*32+32 of kv) ----
        float sa[4][4];
#pragma unroll
        for (int nt = 0; nt < 4; nt++)
#pragma unroll
            for (int i = 0; i < 4; i++) sa[nt][i] = 0.f;
#pragma unroll
        for (int ks = 0; ks < 8; ks++) {
            uint32_t bf[4][2];
#pragma unroll
            for (int nt = 0; nt < 4; nt++) {
                const int kvn = wc * 32 + nt * 8 + g;
                bf[nt][0] = KPs[kvn][ks * 8 + tg];
                bf[nt][1] = KPs[kvn][ks * 8 + tg + 4];
            }
#pragma unroll
            for (int nt = 0; nt < 4; nt++)
                mma_tf32(sa[nt], qa[ks], bf[nt]);
        }
#pragma unroll
        for (int nt = 0; nt < 4; nt++)
#pragma unroll
            for (int i = 0; i < 4; i++) sa[nt][i] *= 0.125f;

        // ---- online softmax (register C-fragments) ----
        float pm0 = -1e30f, pm1 = -1e30f;
#pragma unroll
        for (int nt = 0; nt < 4; nt++) {
            pm0 = fmaxf(pm0, fmaxf(sa[nt][0], sa[nt][1]));
            pm1 = fmaxf(pm1, fmaxf(sa[nt][2], sa[nt][3]));
        }
        pm0 = fmaxf(pm0, __shfl_xor_sync(0xffffffffu, pm0, 1));
        pm0 = fmaxf(pm0, __shfl_xor_sync(0xffffffffu, pm0, 2));
        pm1 = fmaxf(pm1, __shfl_xor_sync(0xffffffffu, pm1, 1));
        pm1 = fmaxf(pm1, __shfl_xor_sync(0xffffffffu, pm1, 2));
        if (tg == 0) { red_max[wc][r0] = pm0; red_max[wc][r1] = pm1; }
        __syncthreads();   // also: all S-MMA reads of KPs are done

        const float mnew0 = fmaxf(m_reg[0], fmaxf(red_max[0][r0], red_max[1][r0]));
        const float mnew1 = fmaxf(m_reg[1], fmaxf(red_max[0][r1], red_max[1][r1]));

        float ps0 = 0.f, ps1 = 0.f;
#pragma unroll
        for (int nt = 0; nt < 4; nt++) {
            const int c = wc * 32 + nt * 8 + 2 * tg;
            const float p00 = __expf(sa[nt][0] - mnew0);
            const float p01 = __expf(sa[nt][1] - mnew0);
            const float p10 = __expf(sa[nt][2] - mnew1);
            const float p11 = __expf(sa[nt][3] - mnew1);
            ps0 += p00 + p01;
            ps1 += p10 + p11;
            KPs[r0][c] = f2tf32(p00); KPs[r0][c + 1] = f2tf32(p01);
            KPs[r1][c] = f2tf32(p10); KPs[r1][c + 1] = f2tf32(p11);
        }
        ps0 += __shfl_xor_sync(0xffffffffu, ps0, 1);
        ps0 += __shfl_xor_sync(0xffffffffu, ps0, 2);
        ps1 += __shfl_xor_sync(0xffffffffu, ps1, 1);
        ps1 += __shfl_xor_sync(0xffffffffu, ps1, 2);
        if (tg == 0) { red_sum[wc][r0] = ps0; red_sum[wc][r1] = ps1; }
        __syncthreads();   // P visible + sums visible

        const float sc0 = __expf(m_reg[0] - mnew0);
        const float sc1 = __expf(m_reg[1] - mnew1);
        l_reg[0] = l_reg[0] * sc0 + red_sum[0][r0] + red_sum[1][r0];
        l_reg[1] = l_reg[1] * sc1 + red_sum[0][r1] + red_sum[1][r1];
        m_reg[0] = mnew0; m_reg[1] = mnew1;
#pragma unroll
        for (int nt = 0; nt < 4; nt++) {
            oa[nt][0] *= sc0; oa[nt][1] *= sc0;
            oa[nt][2] *= sc1; oa[nt][3] *= sc1;
        }

        // ---- O += P @ V (warp: rows wr*16+16, cols wc*32+32 of d) ----
#pragma unroll
        for (int ks = 0; ks < 8; ks++) {
            uint32_t pa[4], bf[4][2];
            pa[0] = KPs[wr * 16 + g    ][ks * 8 + tg];
            pa[1] = KPs[wr * 16 + g + 8][ks * 8 + tg];
            pa[2] = KPs[wr * 16 + g    ][ks * 8 + tg + 4];
            pa[3] = KPs[wr * 16 + g + 8][ks * 8 + tg + 4];
#pragma unroll
            for (int nt = 0; nt < 4; nt++) {
                const int dn = wc * 32 + nt * 8 + g;
                bf[nt][0] = Vs[ks * 8 + tg    ][dn];
                bf[nt][1] = Vs[ks * 8 + tg + 4][dn];
            }
#pragma unroll
            for (int nt = 0; nt < 4; nt++)
                mma_tf32(oa[nt], pa, bf[nt]);
        }
        __syncthreads();   // before next tile overwrites KPs/Vs
    }

    // ---- finalize ----
    const float inv0 = 1.f / l_reg[0];
    const float inv1 = 1.f / l_reg[1];
    float* c0p = ctx + ((size_t)(b * S_LEN) + qt0 + r0) * DM + h * HD;
    float* c1p = ctx + ((size_t)(b * S_LEN) + qt0 + r1) * DM + h * HD;
#pragma unroll
    for (int nt = 0; nt < 4; nt++) {
        const int c = wc * 32 + nt * 8 + 2 * tg;
        c0p[c]     = oa[nt][0] * inv0;
        c0p[c + 1] = oa[nt][1] * inv0;
        c1p[c]     = oa[nt][2] * inv1;
        c1p[c + 1] = oa[nt][3] * inv1;
    }
}

// ---------------------------------------------------------------------------
extern "C" void kernel_launch(void* const* d_in, const int* in_sizes, int n_in,
                              void* d_out, int out_size)
{
    const float* x  = (const float*)d_in[0];
    const float* wq = (const float*)d_in[1];
    const float* bq = (const float*)d_in[2];
    const float* wk = (const float*)d_in[3];
    const float* bk = (const float*)d_in[4];
    const float* wv = (const float*)d_in[5];
    const float* bv = (const float*)d_in[6];
    const float* wo = (const float*)d_in[7];
    const float* bo = (const float*)d_in[8];
    float* out = (float*)d_out;

    float *q = nullptr, *k = nullptr, *v = nullptr, *ctx = nullptr;
    cudaGetSymbolAddress((void**)&q,   g_q);
    cudaGetSymbolAddress((void**)&k,   g_k);
    cudaGetSymbolAddress((void**)&v,   g_v);
    cudaGetSymbolAddress((void**)&ctx, g_ctx);

    dim3 gg(DM / 128, MROWS / 128);      // (8, 32)
    gemm_tf32_kernel<1><<<gg, 256>>>(x, wq, bq, q);
    gemm_tf32_kernel<1><<<gg, 256>>>(x, wk, bk, k);
    gemm_tf32_kernel<1><<<gg, 256>>>(x, wv, bv, v);

    dim3 ga(S_LEN / 64, NH, BATCH);      // (32, 16, 2)
    attn_tf32_kernel<<<ga, 256>>>(q, k, v, ctx);

    gemm_tf32_kernel<0><<<gg, 256>>>(ctx, wo, bo, out);
}

// round 8
// speedup vs baseline: 2.8428x; 1.0206x over previous
#include <cuda_runtime.h>
#include <cstdint>

// ---------------------------------------------------------------------------
// MultiHeadAttention, tf32 tensor cores + cp.async pipelines.
// B=2, S=2048, D=1024, H=16, d=64.
// Pre-convert x/W to tf32 -> merged QKV GEMM -> flash attention -> out GEMM.
// ---------------------------------------------------------------------------

constexpr int S_LEN = 2048;
constexpr int DM    = 1024;
constexpr int NH    = 16;
constexpr int HD    = 64;
constexpr int BATCH = 2;
constexpr int MROWS = BATCH * S_LEN;   // 4096

// Scratch (__device__ globals; allocation-free rule)
__device__ uint32_t g_xt [(size_t)MROWS * DM];          // x as tf32
__device__ uint32_t g_wt [(size_t)4 * DM * DM];         // wq,wk,wv,wo as tf32
__device__ uint32_t g_q  [(size_t)BATCH * NH * S_LEN * HD];  // pre-scaled by 1/8
__device__ uint32_t g_k  [(size_t)BATCH * NH * S_LEN * HD];
__device__ uint32_t g_v  [(size_t)BATCH * NH * S_LEN * HD];
__device__ uint32_t g_ctx[(size_t)MROWS * DM];          // attention out as tf32

__device__ __forceinline__ uint32_t f2tf32(float x) {
    uint32_t u;
    asm("cvt.rna.tf32.f32 %0, %1;" : "=r"(u) : "f"(x));
    return u;
}

__device__ __forceinline__ void mma_tf32(float* c, const uint32_t* a, const uint32_t* b) {
    asm volatile(
        "mma.sync.aligned.m16n8k8.row.col.f32.tf32.tf32.f32 "
        "{%0,%1,%2,%3}, {%4,%5,%6,%7}, {%8,%9}, {%0,%1,%2,%3};"
        : "+f"(c[0]), "+f"(c[1]), "+f"(c[2]), "+f"(c[3])
        : "r"(a[0]), "r"(a[1]), "r"(a[2]), "r"(a[3]), "r"(b[0]), "r"(b[1]));
}

__device__ __forceinline__ void cp_async16(uint32_t smem, const void* g) {
    asm volatile("cp.async.cg.shared.global [%0], [%1], 16;" :: "r"(smem), "l"(g));
}
__device__ __forceinline__ void cp_commit() {
    asm volatile("cp.async.commit_group;");
}
template<int N>
__device__ __forceinline__ void cp_wait() {
    asm volatile("cp.async.wait_group %0;" :: "n"(N));
}

// ---------------------------------------------------------------------------
// Pre-convert x and weights to tf32 bit patterns. float4-vectorized.
// ---------------------------------------------------------------------------
__global__ void __launch_bounds__(256)
convert_kernel(const float4* __restrict__ x,  const float4* __restrict__ wq,
               const float4* __restrict__ wk, const float4* __restrict__ wv,
               const float4* __restrict__ wo)
{
    constexpr int NX = MROWS * DM / 4;      // 1048576
    constexpr int NW = DM * DM / 4;         // 262144
    const int idx = blockIdx.x * 256 + threadIdx.x;
    const float4* src;
    uint4* dst;
    int off;
    if (idx < NX) {
        src = x; dst = (uint4*)g_xt; off = idx;
    } else {
        const int t = (idx - NX) >> 18;     // /NW
        off = (idx - NX) & (NW - 1);
        src = (t == 0) ? wq : (t == 1) ? wk : (t == 2) ? wv : wo;
        dst = (uint4*)(g_wt + (size_t)t * DM * DM);
    }
    const float4 v = src[off];
    uint4 u;
    u.x = f2tf32(v.x); u.y = f2tf32(v.y); u.z = f2tf32(v.z); u.w = f2tf32(v.w);
    dst[off] = u;
}

// ---------------------------------------------------------------------------
// GEMM: C[4096,1024] = A @ W + bias, tf32-in.  128x128 block, 8 warps,
// warp 64x32, BK=8, 4-stage cp.async pipeline.  41.9 KB static smem.
// MODE 0: fp32 row-major out (out projection).
// MODE 1: merged QKV (blockIdx.z picks W/bias/out), tf32 head-split out,
//         z==0 (Q) pre-scaled by 1/8.
// ---------------------------------------------------------------------------
struct GemmSmem {
    uint32_t A[4][128][12];   // [m][k], stride 12 -> frag banks conflict-free
    uint32_t B[4][8][136];    // [k][n], stride 136 -> frag banks conflict-free
};

template<int MODE>
__global__ void __launch_bounds__(256)
gemm_tf32_kernel(const uint32_t* __restrict__ Ag, const uint32_t* __restrict__ Wall,
                 const float* __restrict__ b0, const float* __restrict__ b1,
                 const float* __restrict__ b2,
                 uint32_t* __restrict__ o0, uint32_t* __restrict__ o1,
                 uint32_t* __restrict__ o2, float* __restrict__ fout)
{
    constexpr int K = DM, N = DM;
    __shared__ GemmSmem s;

    const int tid  = threadIdx.x;
    const int warp = tid >> 5, lane = tid & 31;
    const int g    = lane >> 2, tg = lane & 3;
    const int wr   = warp >> 2;            // 0..1
    const int wc   = warp & 3;             // 0..3
    const int brow = blockIdx.y * 128;
    const int bcol = blockIdx.x * 128;
    const int z    = (MODE == 1) ? blockIdx.z : 0;

    const uint32_t* W   = (MODE == 1) ? (Wall + (size_t)z * DM * DM) : Wall;
    const float* bias   = (MODE == 1) ? ((z == 0) ? b0 : (z == 1) ? b1 : b2) : b0;
    uint32_t* outu      = (MODE == 1) ? ((z == 0) ? o0 : (z == 1) ? o1 : o2) : o0;
    const float oscale  = (MODE == 1 && z == 0) ? 0.125f : 1.0f;

    // per-thread cp.async assignments (one 16B chunk each for A and B per k-chunk)
    const int a_row = tid >> 1;            // 0..127
    const int a_c   = (tid & 1) * 4;       // u32 offset 0 or 4
    const int b_k   = tid >> 5;            // 0..7
    const int b_n   = (tid & 31) * 4;      // 0..124

    const uint32_t* ApT = Ag + (size_t)(brow + a_row) * K + a_c;
    const uint32_t* WpT = W + (size_t)b_k * N + bcol + b_n;

    const uint32_t sA = (uint32_t)__cvta_generic_to_shared(&s.A[0][0][0]);
    const uint32_t sB = (uint32_t)__cvta_generic_to_shared(&s.B[0][0][0]);
    constexpr uint32_t A_STAGE = 128 * 12 * 4;
    constexpr uint32_t B_STAGE = 8 * 136 * 4;

    const uint32_t dstA = sA + (a_row * 12 + a_c) * 4;
    const uint32_t dstB = sB + (b_k * 136 + b_n) * 4;

    constexpr int NCHUNK = K / 8;          // 128

    auto issue = [&](int kt) {
        const uint32_t st = (uint32_t)(kt & 3);
        cp_async16(dstA + st * A_STAGE, ApT + kt * 8);
        cp_async16(dstB + st * B_STAGE, WpT + (size_t)kt * 8 * N);
    };

    float acc[4][4][4];
#pragma unroll
    for (int mt = 0; mt < 4; mt++)
#pragma unroll
        for (int nt = 0; nt < 4; nt++)
#pragma unroll
            for (int i = 0; i < 4; i++) acc[mt][nt][i] = 0.f;

    issue(0); cp_commit();
    issue(1); cp_commit();
    issue(2); cp_commit();

    for (int kt = 0; kt < NCHUNK; kt++) {
        cp_wait<2>();
        __syncthreads();
        if (kt + 3 < NCHUNK) issue(kt + 3);
        cp_commit();

        const int st = kt & 3;
        uint32_t a[4][4], b[4][2];
#pragma unroll
        for (int mt = 0; mt < 4; mt++) {
            const int r = wr * 64 + mt * 16 + g;
            a[mt][0] = s.A[st][r    ][tg];
            a[mt][1] = s.A[st][r + 8][tg];
            a[mt][2] = s.A[st][r    ][tg + 4];
            a[mt][3] = s.A[st][r + 8][tg + 4];
        }
#pragma unroll
        for (int nt = 0; nt < 4; nt++) {
            const int c = wc * 32 + nt * 8 + g;
            b[nt][0] = s.B[st][tg    ][c];
            b[nt][1] = s.B[st][tg + 4][c];
        }
#pragma unroll
        for (int mt = 0; mt < 4; mt++)
#pragma unroll
            for (int nt = 0; nt < 4; nt++)
                mma_tf32(acc[mt][nt], a[mt], b[nt]);
    }

    // epilogue
#pragma unroll
    for (int mt = 0; mt < 4; mt++) {
#pragma unroll
        for (int nt = 0; nt < 4; nt++) {
#pragma unroll
            for (int half = 0; half < 2; half++) {
                const int m = brow + wr * 64 + mt * 16 + g + half * 8;
#pragma unroll
                for (int e = 0; e < 2; e++) {
                    const int n = bcol + wc * 32 + nt * 8 + 2 * tg + e;
                    const float v = (acc[mt][nt][half * 2 + e] + bias[n]) * oscale;
                    if (MODE == 0) {
                        fout[(size_t)m * N + n] = v;
                    } else {
                        const int bb = m >> 11, sidx = m & 2047;
                        const int h  = n >> 6,  dd = n & 63;
                        outu[(((size_t)(bb * NH + h) * S_LEN) + sidx) * HD + dd] = f2tf32(v);
                    }
                }
            }
        }
    }
}

// ---------------------------------------------------------------------------
// Flash attention, tf32 in.  Block = 64 q x head x batch, 8 warps (4x2).
// KV tile 64, double-buffered via cp.async.  Q (pre-scaled) in registers.
// Dynamic smem: 89 KB.
// ---------------------------------------------------------------------------
struct AttnSmem {
    uint32_t K[2][64][68];
    uint32_t V[2][64][72];
    uint32_t P[64][68];
    float red_max[2][64];
    float red_sum[2][64];
};

__global__ void __launch_bounds__(256)
attn_tf32_kernel(const uint32_t* __restrict__ Q, const uint32_t* __restrict__ Km,
                 const uint32_t* __restrict__ Vm, uint32_t* __restrict__ ctx)
{
    extern __shared__ char smem_raw[];
    AttnSmem& s = *reinterpret_cast<AttnSmem*>(smem_raw);

    const int tid  = threadIdx.x;
    const int warp = tid >> 5, lane = tid & 31;
    const int g    = lane >> 2, tg = lane & 3;
    const int wr   = warp >> 1;        // 0..3
    const int wc   = warp & 1;         // 0..1
    const int qt0  = blockIdx.x * 64;
    const int h    = blockIdx.y;
    const int b    = blockIdx.z;
    const size_t head_base = (size_t)(b * NH + h) * S_LEN * HD;

    const uint32_t* Kg = Km + head_base;
    const uint32_t* Vg = Vm + head_base;

    // Q A-fragments (already tf32, already scaled by 1/8)
    uint32_t qa[8][4];
    {
        const uint32_t* q0 = Q + head_base + (size_t)(qt0 + wr * 16 + g) * HD;
        const uint32_t* q1 = q0 + 8 * HD;
#pragma unroll
        for (int ks = 0; ks < 8; ks++) {
            qa[ks][0] = q0[ks * 8 + tg];
            qa[ks][1] = q1[ks * 8 + tg];
            qa[ks][2] = q0[ks * 8 + tg + 4];
            qa[ks][3] = q1[ks * 8 + tg + 4];
        }
    }

    const int r0 = wr * 16 + g;
    const int r1 = r0 + 8;
    float m_reg[2] = {-1e30f, -1e30f};
    float l_reg[2] = {0.f, 0.f};
    float oa[4][4];
#pragma unroll
    for (int nt = 0; nt < 4; nt++)
#pragma unroll
        for (int i = 0; i < 4; i++) oa[nt][i] = 0.f;

    const uint32_t sK = (uint32_t)__cvta_generic_to_shared(&s.K[0][0][0]);
    const uint32_t sV = (uint32_t)__cvta_generic_to_shared(&s.V[0][0][0]);
    constexpr uint32_t K_STAGE = 64 * 68 * 4;
    constexpr uint32_t V_STAGE = 64 * 72 * 4;
    constexpr int NTILE = S_LEN / 64;  // 32

    // cp.async load: 64x64 u32 tile = 1024 x 16B chunks, 4 per thread
    auto issue = [&](int kt) {
        const uint32_t st = (uint32_t)(kt & 1);
        const int base = kt * 64;
#pragma unroll
        for (int it = 0; it < 4; it++) {
            const int idx = tid + it * 256;
            const int row = idx >> 4;
            const int c4  = (idx & 15) * 4;
            cp_async16(sK + st * K_STAGE + (row * 68 + c4) * 4,
                       Kg + (size_t)(base + row) * HD + c4);
            cp_async16(sV + st * V_STAGE + (row * 72 + c4) * 4,
                       Vg + (size_t)(base + row) * HD + c4);
        }
    };

    issue(0); cp_commit();

    for (int kt = 0; kt < NTILE; kt++) {
        cp_wait<0>();
        __syncthreads();                    // tile kt visible; prior iter fully done
        if (kt + 1 < NTILE) issue(kt + 1);
        cp_commit();

        const int st = kt & 1;

        // ---- S = Q @ K^T ----
        float sa[4][4];
#pragma unroll
        for (int nt = 0; nt < 4; nt++)
#pragma unroll
            for (int i = 0; i < 4; i++) sa[nt][i] = 0.f;
#pragma unroll
        for (int ks = 0; ks < 8; ks++) {
            uint32_t bf[4][2];
#pragma unroll
            for (int nt = 0; nt < 4; nt++) {
                const int kvn = wc * 32 + nt * 8 + g;
                bf[nt][0] = s.K[st][kvn][ks * 8 + tg];
                bf[nt][1] = s.K[st][kvn][ks * 8 + tg + 4];
            }
#pragma unroll
            for (int nt = 0; nt < 4; nt++)
                mma_tf32(sa[nt], qa[ks], bf[nt]);
        }

        // ---- online softmax ----
        float pm0 = -1e30f, pm1 = -1e30f;
#pragma unroll
        for (int nt = 0; nt < 4; nt++) {
            pm0 = fmaxf(pm0, fmaxf(sa[nt][0], sa[nt][1]));
            pm1 = fmaxf(pm1, fmaxf(sa[nt][2], sa[nt][3]));
        }
        pm0 = fmaxf(pm0, __shfl_xor_sync(0xffffffffu, pm0, 1));
        pm0 = fmaxf(pm0, __shfl_xor_sync(0xffffffffu, pm0, 2));
        pm1 = fmaxf(pm1, __shfl_xor_sync(0xffffffffu, pm1, 1));
        pm1 = fmaxf(pm1, __shfl_xor_sync(0xffffffffu, pm1, 2));
        if (tg == 0) { s.red_max[wc][r0] = pm0; s.red_max[wc][r1] = pm1; }
        __syncthreads();

        const float mnew0 = fmaxf(m_reg[0], fmaxf(s.red_max[0][r0], s.red_max[1][r0]));
        const float mnew1 = fmaxf(m_reg[1], fmaxf(s.red_max[0][r1], s.red_max[1][r1]));

        float ps0 = 0.f, ps1 = 0.f;
#pragma unroll
        for (int nt = 0; nt < 4; nt++) {
            const int c = wc * 32 + nt * 8 + 2 * tg;
            const float p00 = __expf(sa[nt][0] - mnew0);
            const float p01 = __expf(sa[nt][1] - mnew0);
            const float p10 = __expf(sa[nt][2] - mnew1);
            const float p11 = __expf(sa[nt][3] - mnew1);
            ps0 += p00 + p01;
            ps1 += p10 + p11;
            s.P[r0][c] = f2tf32(p00); s.P[r0][c + 1] = f2tf32(p01);
            s.P[r1][c] = f2tf32(p10); s.P[r1][c + 1] = f2tf32(p11);
        }
        ps0 += __shfl_xor_sync(0xffffffffu, ps0, 1);
        ps0 += __shfl_xor_sync(0xffffffffu, ps0, 2);
        ps1 += __shfl_xor_sync(0xffffffffu, ps1, 1);
        ps1 += __shfl_xor_sync(0xffffffffu, ps1, 2);
        if (tg == 0) { s.red_sum[wc][r0] = ps0; s.red_sum[wc][r1] = ps1; }
        __syncthreads();

        const float sc0 = __expf(m_reg[0] - mnew0);
        const float sc1 = __expf(m_reg[1] - mnew1);
        l_reg[0] = l_reg[0] * sc0 + s.red_sum[0][r0] + s.red_sum[1][r0];
        l_reg[1] = l_reg[1] * sc1 + s.red_sum[0][r1] + s.red_sum[1][r1];
        m_reg[0] = mnew0; m_reg[1] = mnew1;
#pragma unroll
        for (int nt = 0; nt < 4; nt++) {
            oa[nt][0] *= sc0; oa[nt][1] *= sc0;
            oa[nt][2] *= sc1; oa[nt][3] *= sc1;
        }

        // ---- O += P @ V ----
#pragma unroll
        for (int ks = 0; ks < 8; ks++) {
            uint32_t pa[4], bf[4][2];
            pa[0] = s.P[wr * 16 + g    ][ks * 8 + tg];
            pa[1] = s.P[wr * 16 + g + 8][ks * 8 + tg];
            pa[2] = s.P[wr * 16 + g    ][ks * 8 + tg + 4];
            pa[3] = s.P[wr * 16 + g + 8][ks * 8 + tg + 4];
#pragma unroll
            for (int nt = 0; nt < 4; nt++) {
                const int dn = wc * 32 + nt * 8 + g;
                bf[nt][0] = s.V[st][ks * 8 + tg    ][dn];
                bf[nt][1] = s.V[st][ks * 8 + tg + 4][dn];
            }
#pragma unroll
            for (int nt = 0; nt < 4; nt++)
                mma_tf32(oa[nt], pa, bf[nt]);
        }
        // no trailing sync: next iteration's top syncthreads protects reuse
    }

    // ---- finalize: /l, write ctx as tf32 ----
    const float inv0 = 1.f / l_reg[0];
    const float inv1 = 1.f / l_reg[1];
    uint32_t* c0p = ctx + ((size_t)(b * S_LEN) + qt0 + r0) * DM + h * HD;
    uint32_t* c1p = ctx + ((size_t)(b * S_LEN) + qt0 + r1) * DM + h * HD;
#pragma unroll
    for (int nt = 0; nt < 4; nt++) {
        const int c = wc * 32 + nt * 8 + 2 * tg;
        c0p[c]     = f2tf32(oa[nt][0] * inv0);
        c0p[c + 1] = f2tf32(oa[nt][1] * inv0);
        c1p[c]     = f2tf32(oa[nt][2] * inv1);
        c1p[c + 1] = f2tf32(oa[nt][3] * inv1);
    }
}

// ---------------------------------------------------------------------------
extern "C" void kernel_launch(void* const* d_in, const int* in_sizes, int n_in,
                              void* d_out, int out_size)
{
    const float* x  = (const float*)d_in[0];
    const float* wq = (const float*)d_in[1];
    const float* bq = (const float*)d_in[2];
    const float* wk = (const float*)d_in[3];
    const float* bk = (const float*)d_in[4];
    const float* wv = (const float*)d_in[5];
    const float* bv = (const float*)d_in[6];
    const float* wo = (const float*)d_in[7];
    const float* bo = (const float*)d_in[8];
    float* out = (float*)d_out;

    uint32_t *xt, *wt, *q, *k, *v, *ctx;
    cudaGetSymbolAddress((void**)&xt,  g_xt);
    cudaGetSymbolAddress((void**)&wt,  g_wt);
    cudaGetSymbolAddress((void**)&q,   g_q);
    cudaGetSymbolAddress((void**)&k,   g_k);
    cudaGetSymbolAddress((void**)&v,   g_v);
    cudaGetSymbolAddress((void**)&ctx, g_ctx);

    cudaFuncSetAttribute(attn_tf32_kernel,
                         cudaFuncAttributeMaxDynamicSharedMemorySize,
                         (int)sizeof(AttnSmem));

    // 1) convert x + weights to tf32
    constexpr int NCONV = (MROWS * DM + 4 * DM * DM) / 4;   // 2M float4
    convert_kernel<<<NCONV / 256, 256>>>((const float4*)x, (const float4*)wq,
                                         (const float4*)wk, (const float4*)wv,
                                         (const float4*)wo);

    // 2) merged QKV projection (z picks q/k/v)
    dim3 gqkv(DM / 128, MROWS / 128, 3);
    gemm_tf32_kernel<1><<<gqkv, 256>>>(xt, wt, bq, bk, bv, q, k, v, nullptr);

    // 3) flash attention
    dim3 ga(S_LEN / 64, NH, BATCH);
    attn_tf32_kernel<<<ga, 256, sizeof(AttnSmem)>>>(q, k, v, ctx);

    // 4) output projection (W offset 3, fp32 out)
    dim3 gg(DM / 128, MROWS / 128);
    gemm_tf32_kernel<0><<<gg, 256>>>(ctx, wt + (size_t)3 * DM * DM,
                                     bo, nullptr, nullptr,
                                     nullptr, nullptr, nullptr, out);
}

// round 10
// speedup vs baseline: 6.0263x; 2.1198x over previous
#include <cuda_runtime.h>
#include <cuda_fp16.h>
#include <cstdint>

// ---------------------------------------------------------------------------
// MultiHeadAttention, fp16 tensor cores (m16n8k16, fp32 accum) + ldmatrix +
// cp.async. B=2, S=2048, D=1024, H=16, d=64.
// ---------------------------------------------------------------------------

constexpr int S_LEN = 2048;
constexpr int DM    = 1024;
constexpr int NH    = 16;
constexpr int HD    = 64;
constexpr int BATCH = 2;
constexpr int MROWS = BATCH * S_LEN;   // 4096

__device__ __half g_xh [(size_t)MROWS * DM];
__device__ __half g_wh [(size_t)4 * DM * DM];
__device__ __half g_q  [(size_t)BATCH * NH * S_LEN * HD];   // pre-scaled 1/8
__device__ __half g_k  [(size_t)BATCH * NH * S_LEN * HD];
__device__ __half g_v  [(size_t)BATCH * NH * S_LEN * HD];
__device__ __half g_ctx[(size_t)MROWS * DM];

__device__ __forceinline__ void mma_f16(float* c, const uint32_t* a, const uint32_t* b) {
    asm volatile(
        "mma.sync.aligned.m16n8k16.row.col.f32.f16.f16.f32 "
        "{%0,%1,%2,%3}, {%4,%5,%6,%7}, {%8,%9}, {%0,%1,%2,%3};"
        : "+f"(c[0]), "+f"(c[1]), "+f"(c[2]), "+f"(c[3])
        : "r"(a[0]), "r"(a[1]), "r"(a[2]), "r"(a[3]), "r"(b[0]), "r"(b[1]));
}
__device__ __forceinline__ void ldsm_x4(uint32_t* r, uint32_t addr) {
    asm volatile("ldmatrix.sync.aligned.m8n8.x4.shared.b16 {%0,%1,%2,%3}, [%4];"
        : "=r"(r[0]), "=r"(r[1]), "=r"(r[2]), "=r"(r[3]) : "r"(addr));
}
__device__ __forceinline__ void ldsm_x4_t(uint32_t* r, uint32_t addr) {
    asm volatile("ldmatrix.sync.aligned.m8n8.x4.trans.shared.b16 {%0,%1,%2,%3}, [%4];"
        : "=r"(r[0]), "=r"(r[1]), "=r"(r[2]), "=r"(r[3]) : "r"(addr));
}
__device__ __forceinline__ void cp_async16(uint32_t smem, const void* g) {
    asm volatile("cp.async.cg.shared.global [%0], [%1], 16;" :: "r"(smem), "l"(g));
}
__device__ __forceinline__ void cp_commit() { asm volatile("cp.async.commit_group;"); }
template<int N> __device__ __forceinline__ void cp_wait() {
    asm volatile("cp.async.wait_group %0;" :: "n"(N));
}
__device__ __forceinline__ uint32_t pack_h2(float a, float b) {
    __half2 h = __floats2half2_rn(a, b);
    return *reinterpret_cast<uint32_t*>(&h);
}

// ---------------------------------------------------------------------------
// Convert x + weights to fp16.  8 floats per thread.
// ---------------------------------------------------------------------------
__global__ void __launch_bounds__(256)
convert_kernel(const float* __restrict__ x,  const float* __restrict__ wq,
               const float* __restrict__ wk, const float* __restrict__ wv,
               const float* __restrict__ wo)
{
    constexpr size_t NX = (size_t)MROWS * DM;      // 4M
    constexpr size_t NW = (size_t)DM * DM;         // 1M
    const size_t i8 = ((size_t)blockIdx.x * 256 + threadIdx.x) * 8;
    const float* src;
    __half* dst;
    if (i8 < NX) { src = x + i8; dst = g_xh + i8; }
    else {
        const size_t r = i8 - NX;
        const int t = (int)(r / NW);
        const size_t off = r % NW;
        src = ((t == 0) ? wq : (t == 1) ? wk : (t == 2) ? wv : wo) + off;
        dst = g_wh + (size_t)t * NW + off;
    }
    float4 a = *(const float4*)(src);
    float4 b = *(const float4*)(src + 4);
    __half2 h[4];
    h[0] = __floats2half2_rn(a.x, a.y); h[1] = __floats2half2_rn(a.z, a.w);
    h[2] = __floats2half2_rn(b.x, b.y); h[3] = __floats2half2_rn(b.z, b.w);
    *(uint4*)dst = *(uint4*)h;
}

// ---------------------------------------------------------------------------
// GEMM fp16: C[4096,1024] = A @ W + bias.  128x128 block, 8 warps (2x4),
// warp 64x32, BK=32, 3-stage cp.async, ldmatrix fragments.
// MODE 0: fp32 row-major out.  MODE 1: merged QKV, half head-split out,
//         z==0 scaled by 1/8.
// ---------------------------------------------------------------------------
struct GemmSmem {
    __half A[3][128][40];     // pad 40: ldmatrix conflict-free (80B rows)
    __half B[3][32][136];     // pad 136: conflict-free (272B rows)
};

template<int MODE>
__global__ void __launch_bounds__(256)
gemm_f16_kernel(const __half* __restrict__ Ag, const __half* __restrict__ Wall,
                const float* __restrict__ b0, const float* __restrict__ b1,
                const float* __restrict__ b2,
                __half* __restrict__ o0, __half* __restrict__ o1,
                __half* __restrict__ o2, float* __restrict__ fout)
{
    constexpr int K = DM, N = DM;
    extern __shared__ char smem_raw[];
    GemmSmem& s = *reinterpret_cast<GemmSmem*>(smem_raw);

    const int tid  = threadIdx.x;
    const int warp = tid >> 5, lane = tid & 31;
    const int g    = lane >> 2, tg = lane & 3;
    const int wr   = warp >> 2;            // 0..1
    const int wc   = warp & 3;             // 0..3
    const int brow = blockIdx.y * 128;
    const int bcol = blockIdx.x * 128;
    const int z    = (MODE == 1) ? blockIdx.z : 0;

    const __half* W    = (MODE == 1) ? (Wall + (size_t)z * DM * DM) : Wall;
    const float* bias  = (MODE == 1) ? ((z == 0) ? b0 : (z == 1) ? b1 : b2) : b0;
    __half* outh       = (MODE == 1) ? ((z == 0) ? o0 : (z == 1) ? o1 : o2) : o0;
    const float oscale = (MODE == 1 && z == 0) ? 0.125f : 1.0f;

    const uint32_t sA = (uint32_t)__cvta_generic_to_shared(&s.A[0][0][0]);
    const uint32_t sB = (uint32_t)__cvta_generic_to_shared(&s.B[0][0][0]);
    constexpr uint32_t A_STAGE = 128 * 40 * 2;   // 10240
    constexpr uint32_t B_STAGE = 32 * 136 * 2;   // 8704

    // cp.async: A 512 chunks (row, 4x8h), B 512 chunks (row, 16x8h); 2+2/thread
    const int ca0 = tid * 2;
    const int cb0 = tid * 2;

    auto issue = [&](int kt) {
        const uint32_t st = (uint32_t)(kt % 3);
#pragma unroll
        for (int i = 0; i < 2; i++) {
            const int ca = ca0 + i, row = ca >> 2, c8 = (ca & 3) * 8;
            cp_async16(sA + st * A_STAGE + (uint32_t)(row * 40 + c8) * 2,
                       Ag + (size_t)(brow + row) * K + kt * 32 + c8);
            const int cb = cb0 + i, rb = cb >> 4, n8 = (cb & 15) * 8;
            cp_async16(sB + st * B_STAGE + (uint32_t)(rb * 136 + n8) * 2,
                       W + (size_t)(kt * 32 + rb) * N + bcol + n8);
        }
    };

    float acc[4][4][4];
#pragma unroll
    for (int mt = 0; mt < 4; mt++)
#pragma unroll
        for (int nt = 0; nt < 4; nt++)
#pragma unroll
            for (int i = 0; i < 4; i++) acc[mt][nt][i] = 0.f;

    issue(0); cp_commit();
    issue(1); cp_commit();

    constexpr int NCHUNK = K / 32;         // 32
    for (int kt = 0; kt < NCHUNK; kt++) {
        cp_wait<1>();
        __syncthreads();
        if (kt + 2 < NCHUNK) issue(kt + 2);
        cp_commit();

        const uint32_t st = (uint32_t)(kt % 3);
        const uint32_t aBase = sA + st * A_STAGE;
        const uint32_t bBase = sB + st * B_STAGE;

#pragma unroll
        for (int ks = 0; ks < 2; ks++) {
            uint32_t a[4][4];
#pragma unroll
            for (int mt = 0; mt < 4; mt++) {
                const int r = wr * 64 + mt * 16 + (lane & 15);
                const int c = ks * 16 + (lane >> 4) * 8;
                ldsm_x4(a[mt], aBase + (uint32_t)(r * 40 + c) * 2);
            }
            uint32_t b[4][2];
#pragma unroll
            for (int ntp = 0; ntp < 2; ntp++) {
                uint32_t bb[4];
                const int rk = ks * 16 + (lane & 15);
                const int nn = wc * 32 + ntp * 16 + (lane >> 4) * 8;
                ldsm_x4_t(bb, bBase + (uint32_t)(rk * 136 + nn) * 2);
                b[2 * ntp][0] = bb[0]; b[2 * ntp][1] = bb[1];
                b[2 * ntp + 1][0] = bb[2]; b[2 * ntp + 1][1] = bb[3];
            }
#pragma unroll
            for (int mt = 0; mt < 4; mt++)
#pragma unroll
                for (int nt = 0; nt < 4; nt++)
                    mma_f16(acc[mt][nt], a[mt], b[nt]);
        }
    }

    // epilogue
#pragma unroll
    for (int mt = 0; mt < 4; mt++) {
#pragma unroll
        for (int nt = 0; nt < 4; nt++) {
#pragma unroll
            for (int half = 0; half < 2; half++) {
                const int m = brow + wr * 64 + mt * 16 + g + half * 8;
                const int n = bcol + wc * 32 + nt * 8 + 2 * tg;
                const float v0 = (acc[mt][nt][half * 2 + 0] + bias[n])     * oscale;
                const float v1 = (acc[mt][nt][half * 2 + 1] + bias[n + 1]) * oscale;
                if (MODE == 0) {
                    *(float2*)&fout[(size_t)m * N + n] = make_float2(v0, v1);
                } else {
                    const int bb = m >> 11, sidx = m & 2047;
                    const int h  = n >> 6,  dd = n & 63;
                    *(uint32_t*)&outh[(((size_t)(bb * NH + h) * S_LEN) + sidx) * HD + dd]
                        = pack_h2(v0, v1);
                }
            }
        }
    }
}

// ---------------------------------------------------------------------------
// Flash attention fp16.  Block = 64 q x head x batch, 8 warps (wr 0-3, wc 0-1).
// KV tile 64, double-buffered cp.async.  Q frags from gmem.  P stays in regs.
// Each warp accumulates O over its kv-half; cross-warp add at the end.
// ---------------------------------------------------------------------------
struct AttnSmem {
    union {
        __half K[2][64][72];        // 18432 B (144B rows, conflict-free)
        float  ored[4096];          // 16384 B, used only in final reduction
    } k;
    __half V[2][64][72];
    float red_max[2][64];
    float red_sum[2][64];
};

__global__ void __launch_bounds__(256)
attn_f16_kernel(const __half* __restrict__ Q, const __half* __restrict__ Km,
                const __half* __restrict__ Vm, __half* __restrict__ ctx)
{
    __shared__ AttnSmem s;

    const int tid  = threadIdx.x;
    const int warp = tid >> 5, lane = tid & 31;
    const int g    = lane >> 2, tg = lane & 3;
    const int wr   = warp >> 1;        // 0..3
    const int wc   = warp & 1;         // 0..1
    const int qt0  = blockIdx.x * 64;
    const int h    = blockIdx.y;
    const int b    = blockIdx.z;
    const size_t head_base = (size_t)(b * NH + h) * S_LEN * HD;

    const __half* Kg = Km + head_base;
    const __half* Vg = Vm + head_base;

    // Q A-fragments (fp16, pre-scaled): rows wr*16+{g,g+8}, 4 k16 chunks
    uint32_t qa[4][4];
    {
        const __half* q0 = Q + head_base + (size_t)(qt0 + wr * 16 + g) * HD;
        const __half* q1 = q0 + 8 * HD;
#pragma unroll
        for (int ks = 0; ks < 4; ks++) {
            qa[ks][0] = *(const uint32_t*)&q0[ks * 16 + 2 * tg];
            qa[ks][1] = *(const uint32_t*)&q1[ks * 16 + 2 * tg];
            qa[ks][2] = *(const uint32_t*)&q0[ks * 16 + 8 + 2 * tg];
            qa[ks][3] = *(const uint32_t*)&q1[ks * 16 + 8 + 2 * tg];
        }
    }

    const int r0 = wr * 16 + g;
    const int r1 = r0 + 8;
    float m_reg[2] = {-1e30f, -1e30f};
    float l_reg[2] = {0.f, 0.f};
    float oa[8][4];
#pragma unroll
    for (int nt = 0; nt < 8; nt++)
#pragma unroll
        for (int i = 0; i < 4; i++) oa[nt][i] = 0.f;

    const uint32_t sK = (uint32_t)__cvta_generic_to_shared(&s.k.K[0][0][0]);
    const uint32_t sV = (uint32_t)__cvta_generic_to_shared(&s.V[0][0][0]);
    constexpr uint32_t KV_STAGE = 64 * 72 * 2;   // 9216
    constexpr int NTILE = S_LEN / 64;            // 32

    // cp.async: K,V each 512 chunks (64 rows x 8 x 8h); 2+2 per thread
    auto issue = [&](int kt) {
        const uint32_t st = (uint32_t)(kt & 1);
        const int base = kt * 64;
#pragma unroll
        for (int i = 0; i < 2; i++) {
            const int idx = tid * 2 + i;
            const int row = idx >> 3, c8 = (idx & 7) * 8;
            const size_t goff = (size_t)(base + row) * HD + c8;
            const uint32_t soff = (uint32_t)(row * 72 + c8) * 2;
            cp_async16(sK + st * KV_STAGE + soff, Kg + goff);
            cp_async16(sV + st * KV_STAGE + soff, Vg + goff);
        }
    };

    issue(0); cp_commit();

    for (int kt = 0; kt < NTILE; kt++) {
        cp_wait<0>();
        __syncthreads();
        if (kt + 1 < NTILE) issue(kt + 1);
        cp_commit();

        const uint32_t st = (uint32_t)(kt & 1);
        const uint32_t kBase = sK + st * KV_STAGE;
        const uint32_t vBase = sV + st * KV_STAGE;

        // ---- S = Q @ K^T : warp covers kv cols wc*32..+32 ----
        float sa[4][4];
#pragma unroll
        for (int nt = 0; nt < 4; nt++)
#pragma unroll
            for (int i = 0; i < 4; i++) sa[nt][i] = 0.f;
#pragma unroll
        for (int p = 0; p < 2; p++) {          // d chunks of 32
#pragma unroll
            for (int nt = 0; nt < 4; nt++) {
                uint32_t kb[4];
                const int kvr = wc * 32 + nt * 8 + (lane & 7);
                const int d   = p * 32 + (lane >> 3) * 8;
                ldsm_x4(kb, kBase + (uint32_t)(kvr * 72 + d) * 2);
                mma_f16(sa[nt], qa[2 * p],     kb);       // d chunk 2p
                mma_f16(sa[nt], qa[2 * p + 1], kb + 2);   // d chunk 2p+1
            }
        }

        // ---- online softmax (C-fragment layout) ----
        float pm0 = -1e30f, pm1 = -1e30f;
#pragma unroll
        for (int nt = 0; nt < 4; nt++) {
            pm0 = fmaxf(pm0, fmaxf(sa[nt][0], sa[nt][1]));
            pm1 = fmaxf(pm1, fmaxf(sa[nt][2], sa[nt][3]));
        }
        pm0 = fmaxf(pm0, __shfl_xor_sync(0xffffffffu, pm0, 1));
        pm0 = fmaxf(pm0, __shfl_xor_sync(0xffffffffu, pm0, 2));
        pm1 = fmaxf(pm1, __shfl_xor_sync(0xffffffffu, pm1, 1));
        pm1 = fmaxf(pm1, __shfl_xor_sync(0xffffffffu, pm1, 2));
        if (tg == 0) { s.red_max[wc][r0] = pm0; s.red_max[wc][r1] = pm1; }
        __syncthreads();

        const float mnew0 = fmaxf(m_reg[0], fmaxf(s.red_max[0][r0], s.red_max[1][r0]));
        const float mnew1 = fmaxf(m_reg[1], fmaxf(s.red_max[0][r1], s.red_max[1][r1]));

        float ep[4][4];
        float ps0 = 0.f, ps1 = 0.f;
#pragma unroll
        for (int nt = 0; nt < 4; nt++) {
            ep[nt][0] = __expf(sa[nt][0] - mnew0);
            ep[nt][1] = __expf(sa[nt][1] - mnew0);
            ep[nt][2] = __expf(sa[nt][2] - mnew1);
            ep[nt][3] = __expf(sa[nt][3] - mnew1);
            ps0 += ep[nt][0] + ep[nt][1];
            ps1 += ep[nt][2] + ep[nt][3];
        }
        ps0 += __shfl_xor_sync(0xffffffffu, ps0, 1);
        ps0 += __shfl_xor_sync(0xffffffffu, ps0, 2);
        ps1 += __shfl_xor_sync(0xffffffffu, ps1, 1);
        ps1 += __shfl_xor_sync(0xffffffffu, ps1, 2);
        if (tg == 0) { s.red_sum[wc][r0] = ps0; s.red_sum[wc][r1] = ps1; }
        __syncthreads();

        const float sc0 = __expf(m_reg[0] - mnew0);
        const float sc1 = __expf(m_reg[1] - mnew1);
        l_reg[0] = l_reg[0] * sc0 + s.red_sum[0][r0] + s.red_sum[1][r0];
        l_reg[1] = l_reg[1] * sc1 + s.red_sum[0][r1] + s.red_sum[1][r1];
        m_reg[0] = mnew0; m_reg[1] = mnew1;
#pragma unroll
        for (int nt = 0; nt < 8; nt++) {
            oa[nt][0] *= sc0; oa[nt][1] *= sc0;
            oa[nt][2] *= sc1; oa[nt][3] *= sc1;
        }

        // ---- O += P @ V : P packed in regs (C->A frag identity) ----
#pragma unroll
        for (int p = 0; p < 2; p++) {          // warp-local kv chunks of 16
            uint32_t pa[4];
            pa[0] = pack_h2(ep[2 * p][0],     ep[2 * p][1]);
            pa[1] = pack_h2(ep[2 * p][2],     ep[2 * p][3]);
            pa[2] = pack_h2(ep[2 * p + 1][0], ep[2 * p + 1][1]);
            pa[3] = pack_h2(ep[2 * p + 1][2], ep[2 * p + 1][3]);
#pragma unroll
            for (int ntp = 0; ntp < 4; ntp++) {   // d tile pairs (16 each)
                uint32_t vb[4];
                const int kvr = wc * 32 + p * 16 + (lane & 15);
                const int d   = ntp * 16 + (lane >> 4) * 8;
                ldsm_x4_t(vb, vBase + (uint32_t)(kvr * 72 + d) * 2);
                mma_f16(oa[2 * ntp],     pa, vb);
                mma_f16(oa[2 * ntp + 1], pa, vb + 2);
            }
        }
    }

    // ---- cross-warp O reduction (wc halves) + writeout ----
    __syncthreads();
    float* ored = s.k.ored;
    if (wc == 1) {
#pragma unroll
        for (int nt = 0; nt < 8; nt++)
#pragma unroll
            for (int i = 0; i < 4; i++)
                ored[((wr * 32 + lane) * 32) + nt * 4 + i] = oa[nt][i];
    }
    __syncthreads();
    if (wc == 0) {
        const float inv0 = 1.f / l_reg[0];
        const float inv1 = 1.f / l_reg[1];
        __half* c0p = ctx + ((size_t)(b * S_LEN) + qt0 + r0) * DM + h * HD;
        __half* c1p = ctx + ((size_t)(b * S_LEN) + qt0 + r1) * DM + h * HD;
#pragma unroll
        for (int nt = 0; nt < 8; nt++) {
            const float* o2 = &ored[((wr * 32 + lane) * 32) + nt * 4];
            const int c = nt * 8 + 2 * tg;
            *(uint32_t*)&c0p[c] = pack_h2((oa[nt][0] + o2[0]) * inv0,
                                          (oa[nt][1] + o2[1]) * inv0);
            *(uint32_t*)&c1p[c] = pack_h2((oa[nt][2] + o2[2]) * inv1,
                                          (oa[nt][3] + o2[3]) * inv1);
        }
    }
}

// ---------------------------------------------------------------------------
extern "C" void kernel_launch(void* const* d_in, const int* in_sizes, int n_in,
                              void* d_out, int out_size)
{
    const float* x  = (const float*)d_in[0];
    const float* wq = (const float*)d_in[1];
    const float* bq = (const float*)d_in[2];
    const float* wk = (const float*)d_in[3];
    const float* bk = (const float*)d_in[4];
    const float* wv = (const float*)d_in[5];
    const float* bv = (const float*)d_in[6];
    const float* wo = (const float*)d_in[7];
    const float* bo = (const float*)d_in[8];
    float* out = (float*)d_out;

    __half *xh, *wh, *q, *k, *v, *ctx;
    cudaGetSymbolAddress((void**)&xh,  g_xh);
    cudaGetSymbolAddress((void**)&wh,  g_wh);
    cudaGetSymbolAddress((void**)&q,   g_q);
    cudaGetSymbolAddress((void**)&k,   g_k);
    cudaGetSymbolAddress((void**)&v,   g_v);
    cudaGetSymbolAddress((void**)&ctx, g_ctx);

    constexpr int GSM = (int)sizeof(GemmSmem);
    cudaFuncSetAttribute(gemm_f16_kernel<0>,
                         cudaFuncAttributeMaxDynamicSharedMemorySize, GSM);
    cudaFuncSetAttribute(gemm_f16_kernel<1>,
                         cudaFuncAttributeMaxDynamicSharedMemorySize, GSM);

    // 1) fp16 conversion: (4M + 4M) / 8 = 1M threads
    constexpr int NCONV = (int)(((size_t)MROWS * DM + 4 * (size_t)DM * DM) / 8);
    convert_kernel<<<NCONV / 256, 256>>>(x, wq, wk, wv, wo);

    // 2) merged QKV projection
    dim3 gqkv(DM / 128, MROWS / 128, 3);
    gemm_f16_kernel<1><<<gqkv, 256, GSM>>>(xh, wh, bq, bk, bv, q, k, v, nullptr);

    // 3) flash attention
    dim3 ga(S_LEN / 64, NH, BATCH);
    attn_f16_kernel<<<ga, 256>>>(q, k, v, ctx);

    // 4) output projection
    dim3 gg(DM / 128, MROWS / 128);
    gemm_f16_kernel<0><<<gg, 256, GSM>>>(ctx, wh + (size_t)3 * DM * DM,
                                         bo, nullptr, nullptr,
                                         nullptr, nullptr, nullptr, out);
}

// round 11
// speedup vs baseline: 6.9193x; 1.1482x over previous
#include <cuda_runtime.h>
#include <cuda_fp16.h>
#include <cstdint>

// ---------------------------------------------------------------------------
// MultiHeadAttention, fp16 tensor cores (m16n8k16, fp32 accum) + ldmatrix +
// cp.async.  B=2, S=2048, D=1024, H=16, d=64.
// R11: warp-local-softmax attention (128q blocks), 4-stage GEMM pipeline.
// ---------------------------------------------------------------------------

constexpr int S_LEN = 2048;
constexpr int DM    = 1024;
constexpr int NH    = 16;
constexpr int HD    = 64;
constexpr int BATCH = 2;
constexpr int MROWS = BATCH * S_LEN;   // 4096

__device__ __half g_xh [(size_t)MROWS * DM];
__device__ __half g_wh [(size_t)4 * DM * DM];
__device__ __half g_q  [(size_t)BATCH * NH * S_LEN * HD];   // pre-scaled 1/8
__device__ __half g_k  [(size_t)BATCH * NH * S_LEN * HD];
__device__ __half g_v  [(size_t)BATCH * NH * S_LEN * HD];
__device__ __half g_ctx[(size_t)MROWS * DM];

__device__ __forceinline__ void mma_f16(float* c, const uint32_t* a, const uint32_t* b) {
    asm volatile(
        "mma.sync.aligned.m16n8k16.row.col.f32.f16.f16.f32 "
        "{%0,%1,%2,%3}, {%4,%5,%6,%7}, {%8,%9}, {%0,%1,%2,%3};"
        : "+f"(c[0]), "+f"(c[1]), "+f"(c[2]), "+f"(c[3])
        : "r"(a[0]), "r"(a[1]), "r"(a[2]), "r"(a[3]), "r"(b[0]), "r"(b[1]));
}
__device__ __forceinline__ void ldsm_x4(uint32_t* r, uint32_t addr) {
    asm volatile("ldmatrix.sync.aligned.m8n8.x4.shared.b16 {%0,%1,%2,%3}, [%4];"
        : "=r"(r[0]), "=r"(r[1]), "=r"(r[2]), "=r"(r[3]) : "r"(addr));
}
__device__ __forceinline__ void ldsm_x4_t(uint32_t* r, uint32_t addr) {
    asm volatile("ldmatrix.sync.aligned.m8n8.x4.trans.shared.b16 {%0,%1,%2,%3}, [%4];"
        : "=r"(r[0]), "=r"(r[1]), "=r"(r[2]), "=r"(r[3]) : "r"(addr));
}
__device__ __forceinline__ void cp_async16(uint32_t smem, const void* g) {
    asm volatile("cp.async.cg.shared.global [%0], [%1], 16;" :: "r"(smem), "l"(g));
}
__device__ __forceinline__ void cp_commit() { asm volatile("cp.async.commit_group;"); }
template<int N> __device__ __forceinline__ void cp_wait() {
    asm volatile("cp.async.wait_group %0;" :: "n"(N));
}
__device__ __forceinline__ uint32_t pack_h2(float a, float b) {
    __half2 h = __floats2half2_rn(a, b);
    return *reinterpret_cast<uint32_t*>(&h);
}

// ---------------------------------------------------------------------------
// Convert x + weights to fp16.  8 floats per thread.
// ---------------------------------------------------------------------------
__global__ void __launch_bounds__(256)
convert_kernel(const float* __restrict__ x,  const float* __restrict__ wq,
               const float* __restrict__ wk, const float* __restrict__ wv,
               const float* __restrict__ wo)
{
    constexpr size_t NX = (size_t)MROWS * DM;      // 4M
    constexpr size_t NW = (size_t)DM * DM;         // 1M
    const size_t i8 = ((size_t)blockIdx.x * 256 + threadIdx.x) * 8;
    const float* src;
    __half* dst;
    if (i8 < NX) { src = x + i8; dst = g_xh + i8; }
    else {
        const size_t r = i8 - NX;
        const int t = (int)(r / NW);
        const size_t off = r % NW;
        src = ((t == 0) ? wq : (t == 1) ? wk : (t == 2) ? wv : wo) + off;
        dst = g_wh + (size_t)t * NW + off;
    }
    float4 a = *(const float4*)(src);
    float4 b = *(const float4*)(src + 4);
    __half2 h[4];
    h[0] = __floats2half2_rn(a.x, a.y); h[1] = __floats2half2_rn(a.z, a.w);
    h[2] = __floats2half2_rn(b.x, b.y); h[3] = __floats2half2_rn(b.z, b.w);
    *(uint4*)dst = *(uint4*)h;
}

// ---------------------------------------------------------------------------
// GEMM fp16: C[4096,1024] = A @ W + bias.  128x128 block, 8 warps (2x4),
// warp 64x32, BK=32, 4-stage cp.async, ldmatrix fragments.
// MODE 0: fp32 row-major out.  MODE 1: merged QKV, half head-split out,
//         z==0 scaled by 1/8.
// ---------------------------------------------------------------------------
struct GemmSmem {
    __half A[4][128][40];     // pad 40: ldmatrix conflict-free
    __half B[4][32][136];     // pad 136: conflict-free
};

template<int MODE>
__global__ void __launch_bounds__(256)
gemm_f16_kernel(const __half* __restrict__ Ag, const __half* __restrict__ Wall,
                const float* __restrict__ b0, const float* __restrict__ b1,
                const float* __restrict__ b2,
                __half* __restrict__ o0, __half* __restrict__ o1,
                __half* __restrict__ o2, float* __restrict__ fout)
{
    constexpr int K = DM, N = DM;
    extern __shared__ char smem_raw[];
    GemmSmem& s = *reinterpret_cast<GemmSmem*>(smem_raw);

    const int tid  = threadIdx.x;
    const int warp = tid >> 5, lane = tid & 31;
    const int g    = lane >> 2, tg = lane & 3;
    const int wr   = warp >> 2;            // 0..1
    const int wc   = warp & 3;             // 0..3
    const int brow = blockIdx.y * 128;
    const int bcol = blockIdx.x * 128;
    const int z    = (MODE == 1) ? blockIdx.z : 0;

    const __half* W    = (MODE == 1) ? (Wall + (size_t)z * DM * DM) : Wall;
    const float* bias  = (MODE == 1) ? ((z == 0) ? b0 : (z == 1) ? b1 : b2) : b0;
    __half* outh       = (MODE == 1) ? ((z == 0) ? o0 : (z == 1) ? o1 : o2) : o0;
    const float oscale = (MODE == 1 && z == 0) ? 0.125f : 1.0f;

    const uint32_t sA = (uint32_t)__cvta_generic_to_shared(&s.A[0][0][0]);
    const uint32_t sB = (uint32_t)__cvta_generic_to_shared(&s.B[0][0][0]);
    constexpr uint32_t A_STAGE = 128 * 40 * 2;   // 10240
    constexpr uint32_t B_STAGE = 32 * 136 * 2;   // 8704

    const int ca0 = tid * 2;
    const int cb0 = tid * 2;

    auto issue = [&](int kt) {
        const uint32_t st = (uint32_t)(kt & 3);
#pragma unroll
        for (int i = 0; i < 2; i++) {
            const int ca = ca0 + i, row = ca >> 2, c8 = (ca & 3) * 8;
            cp_async16(sA + st * A_STAGE + (uint32_t)(row * 40 + c8) * 2,
                       Ag + (size_t)(brow + row) * K + kt * 32 + c8);
            const int cb = cb0 + i, rb = cb >> 4, n8 = (cb & 15) * 8;
            cp_async16(sB + st * B_STAGE + (uint32_t)(rb * 136 + n8) * 2,
                       W + (size_t)(kt * 32 + rb) * N + bcol + n8);
        }
    };

    float acc[4][4][4];
#pragma unroll
    for (int mt = 0; mt < 4; mt++)
#pragma unroll
        for (int nt = 0; nt < 4; nt++)
#pragma unroll
            for (int i = 0; i < 4; i++) acc[mt][nt][i] = 0.f;

    issue(0); cp_commit();
    issue(1); cp_commit();
    issue(2); cp_commit();

    constexpr int NCHUNK = K / 32;         // 32
    for (int kt = 0; kt < NCHUNK; kt++) {
        cp_wait<2>();
        __syncthreads();
        if (kt + 3 < NCHUNK) issue(kt + 3);
        cp_commit();

        const uint32_t st = (uint32_t)(kt & 3);
        const uint32_t aBase = sA + st * A_STAGE;
        const uint32_t bBase = sB + st * B_STAGE;

#pragma unroll
        for (int ks = 0; ks < 2; ks++) {
            uint32_t a[4][4];
#pragma unroll
            for (int mt = 0; mt < 4; mt++) {
                const int r = wr * 64 + mt * 16 + (lane & 15);
                const int c = ks * 16 + (lane >> 4) * 8;
                ldsm_x4(a[mt], aBase + (uint32_t)(r * 40 + c) * 2);
            }
            uint32_t b[4][2];
#pragma unroll
            for (int ntp = 0; ntp < 2; ntp++) {
                uint32_t bb[4];
                const int rk = ks * 16 + (lane & 15);
                const int nn = wc * 32 + ntp * 16 + (lane >> 4) * 8;
                ldsm_x4_t(bb, bBase + (uint32_t)(rk * 136 + nn) * 2);
                b[2 * ntp][0] = bb[0]; b[2 * ntp][1] = bb[1];
                b[2 * ntp + 1][0] = bb[2]; b[2 * ntp + 1][1] = bb[3];
            }
#pragma unroll
            for (int mt = 0; mt < 4; mt++)
#pragma unroll
                for (int nt = 0; nt < 4; nt++)
                    mma_f16(acc[mt][nt], a[mt], b[nt]);
        }
    }

    // epilogue
#pragma unroll
    for (int mt = 0; mt < 4; mt++) {
#pragma unroll
        for (int nt = 0; nt < 4; nt++) {
#pragma unroll
            for (int half = 0; half < 2; half++) {
                const int m = brow + wr * 64 + mt * 16 + g + half * 8;
                const int n = bcol + wc * 32 + nt * 8 + 2 * tg;
                const float v0 = (acc[mt][nt][half * 2 + 0] + bias[n])     * oscale;
                const float v1 = (acc[mt][nt][half * 2 + 1] + bias[n + 1]) * oscale;
                if (MODE == 0) {
                    *(float2*)&fout[(size_t)m * N + n] = make_float2(v0, v1);
                } else {
                    const int bb = m >> 11, sidx = m & 2047;
                    const int h  = n >> 6,  dd = n & 63;
                    *(uint32_t*)&outh[(((size_t)(bb * NH + h) * S_LEN) + sidx) * HD + dd]
                        = pack_h2(v0, v1);
                }
            }
        }
    }
}

// ---------------------------------------------------------------------------
// Flash attention fp16.  Block = 128 q x head x batch, 8 warps; each warp
// owns 16 q-rows x FULL kv tile -> softmax entirely warp-local (shfl over
// the 4 tg lanes).  One __syncthreads per KV tile.  KV tile 64, cp.async
// double buffer.  P packed in regs (S C-frag -> A-frag identity).
// ---------------------------------------------------------------------------
struct AttnSmem {
    __half K[2][64][72];   // 18432 B (144B rows: 8-row ldsm conflict-free)
    __half V[2][64][72];
};

__global__ void __launch_bounds__(256, 2)
attn_f16_kernel(const __half* __restrict__ Q, const __half* __restrict__ Km,
                const __half* __restrict__ Vm, __half* __restrict__ ctx)
{
    __shared__ AttnSmem s;

    const int tid  = threadIdx.x;
    const int warp = tid >> 5, lane = tid & 31;
    const int g    = lane >> 2, tg = lane & 3;
    const int qt0  = blockIdx.x * 128;
    const int h    = blockIdx.y;
    const int b    = blockIdx.z;
    const size_t head_base = (size_t)(b * NH + h) * S_LEN * HD;

    const __half* Kg = Km + head_base;
    const __half* Vg = Vm + head_base;

    // Q A-fragments (fp16, pre-scaled 1/8): warp rows qt0+warp*16+{g,g+8}
    uint32_t qa[4][4];
    {
        const __half* q0 = Q + head_base + (size_t)(qt0 + warp * 16 + g) * HD;
        const __half* q1 = q0 + 8 * HD;
#pragma unroll
        for (int ks = 0; ks < 4; ks++) {
            qa[ks][0] = *(const uint32_t*)&q0[ks * 16 + 2 * tg];
            qa[ks][1] = *(const uint32_t*)&q1[ks * 16 + 2 * tg];
            qa[ks][2] = *(const uint32_t*)&q0[ks * 16 + 8 + 2 * tg];
            qa[ks][3] = *(const uint32_t*)&q1[ks * 16 + 8 + 2 * tg];
        }
    }

    float m0 = -1e30f, m1 = -1e30f;
    float l0 = 0.f, l1 = 0.f;
    float oa[8][4];
#pragma unroll
    for (int nt = 0; nt < 8; nt++)
#pragma unroll
        for (int i = 0; i < 4; i++) oa[nt][i] = 0.f;

    const uint32_t sK = (uint32_t)__cvta_generic_to_shared(&s.K[0][0][0]);
    const uint32_t sV = (uint32_t)__cvta_generic_to_shared(&s.V[0][0][0]);
    constexpr uint32_t KV_STAGE = 64 * 72 * 2;   // 9216
    constexpr int NTILE = S_LEN / 64;            // 32

    // cp.async: K,V each 512 x 16B chunks; 2+2 per thread
    auto issue = [&](int kt) {
        const uint32_t st = (uint32_t)(kt & 1);
        const int base = kt * 64;
#pragma unroll
        for (int i = 0; i < 2; i++) {
            const int idx = tid * 2 + i;
            const int row = idx >> 3, c8 = (idx & 7) * 8;
            const size_t goff = (size_t)(base + row) * HD + c8;
            const uint32_t soff = (uint32_t)(row * 72 + c8) * 2;
            cp_async16(sK + st * KV_STAGE + soff, Kg + goff);
            cp_async16(sV + st * KV_STAGE + soff, Vg + goff);
        }
    };

    issue(0); cp_commit();

    for (int kt = 0; kt < NTILE; kt++) {
        cp_wait<0>();
        __syncthreads();                  // tile kt ready; all warps past kt-1
        if (kt + 1 < NTILE) issue(kt + 1);
        cp_commit();

        const uint32_t st = (uint32_t)(kt & 1);
        const uint32_t kBase = sK + st * KV_STAGE;
        const uint32_t vBase = sV + st * KV_STAGE;

        // ---- S = Q @ K^T : 16 q-rows x 64 kv per warp ----
        float sa[8][4];
#pragma unroll
        for (int nt = 0; nt < 8; nt++)
#pragma unroll
            for (int i = 0; i < 4; i++) sa[nt][i] = 0.f;
#pragma unroll
        for (int p = 0; p < 2; p++) {          // d chunks of 32
#pragma unroll
            for (int nt = 0; nt < 8; nt++) {   // kv 8-row groups
                uint32_t kb[4];
                const int kvr = nt * 8 + (lane & 7);
                const int d   = p * 32 + (lane >> 3) * 8;
                ldsm_x4(kb, kBase + (uint32_t)(kvr * 72 + d) * 2);
                mma_f16(sa[nt], qa[2 * p],     kb);
                mma_f16(sa[nt], qa[2 * p + 1], kb + 2);
            }
        }

        // ---- warp-local online softmax (rows g / g+8; 4 tg lanes/row) ----
        float pm0 = -1e30f, pm1 = -1e30f;
#pragma unroll
        for (int nt = 0; nt < 8; nt++) {
            pm0 = fmaxf(pm0, fmaxf(sa[nt][0], sa[nt][1]));
            pm1 = fmaxf(pm1, fmaxf(sa[nt][2], sa[nt][3]));
        }
        pm0 = fmaxf(pm0, __shfl_xor_sync(0xffffffffu, pm0, 1));
        pm0 = fmaxf(pm0, __shfl_xor_sync(0xffffffffu, pm0, 2));
        pm1 = fmaxf(pm1, __shfl_xor_sync(0xffffffffu, pm1, 1));
        pm1 = fmaxf(pm1, __shfl_xor_sync(0xffffffffu, pm1, 2));

        const float mnew0 = fmaxf(m0, pm0);
        const float mnew1 = fmaxf(m1, pm1);
        const float sc0 = __expf(m0 - mnew0);
        const float sc1 = __expf(m1 - mnew1);

        float ps0 = 0.f, ps1 = 0.f;
#pragma unroll
        for (int nt = 0; nt < 8; nt++) {
            sa[nt][0] = __expf(sa[nt][0] - mnew0);
            sa[nt][1] = __expf(sa[nt][1] - mnew0);
            sa[nt][2] = __expf(sa[nt][2] - mnew1);
            sa[nt][3] = __expf(sa[nt][3] - mnew1);
            ps0 += sa[nt][0] + sa[nt][1];
            ps1 += sa[nt][2] + sa[nt][3];
        }
        ps0 += __shfl_xor_sync(0xffffffffu, ps0, 1);
        ps0 += __shfl_xor_sync(0xffffffffu, ps0, 2);
        ps1 += __shfl_xor_sync(0xffffffffu, ps1, 1);
        ps1 += __shfl_xor_sync(0xffffffffu, ps1, 2);

        l0 = l0 * sc0 + ps0;
        l1 = l1 * sc1 + ps1;
        m0 = mnew0; m1 = mnew1;
#pragma unroll
        for (int nt = 0; nt < 8; nt++) {
            oa[nt][0] *= sc0; oa[nt][1] *= sc0;
            oa[nt][2] *= sc1; oa[nt][3] *= sc1;
        }

        // ---- O += P @ V : P from regs (C->A frag identity) ----
#pragma unroll
        for (int p = 0; p < 4; p++) {          // kv chunks of 16
            uint32_t pa[4];
            pa[0] = pack_h2(sa[2 * p][0],     sa[2 * p][1]);
            pa[1] = pack_h2(sa[2 * p][2],     sa[2 * p][3]);
            pa[2] = pack_h2(sa[2 * p + 1][0], sa[2 * p + 1][1]);
            pa[3] = pack_h2(sa[2 * p + 1][2], sa[2 * p + 1][3]);
#pragma unroll
            for (int ntp = 0; ntp < 4; ntp++) {   // d tile pairs (16 each)
                uint32_t vb[4];
                const int kvr = p * 16 + (lane & 15);
                const int d   = ntp * 16 + (lane >> 4) * 8;
                ldsm_x4_t(vb, vBase + (uint32_t)(kvr * 72 + d) * 2);
                mma_f16(oa[2 * ntp],     pa, vb);
                mma_f16(oa[2 * ntp + 1], pa, vb + 2);
            }
        }
    }

    // ---- finalize: /l, write ctx (half, concat layout) ----
    const float inv0 = 1.f / l0;
    const float inv1 = 1.f / l1;
    __half* c0p = ctx + ((size_t)(b * S_LEN) + qt0 + warp * 16 + g) * DM + h * HD;
    __half* c1p = c0p + 8 * DM;
#pragma unroll
    for (int nt = 0; nt < 8; nt++) {
        const int c = nt * 8 + 2 * tg;
        *(uint32_t*)&c0p[c] = pack_h2(oa[nt][0] * inv0, oa[nt][1] * inv0);
        *(uint32_t*)&c1p[c] = pack_h2(oa[nt][2] * inv1, oa[nt][3] * inv1);
    }
}

// ---------------------------------------------------------------------------
extern "C" void kernel_launch(void* const* d_in, const int* in_sizes, int n_in,
                              void* d_out, int out_size)
{
    const float* x  = (const float*)d_in[0];
    const float* wq = (const float*)d_in[1];
    const float* bq = (const float*)d_in[2];
    const float* wk = (const float*)d_in[3];
    const float* bk = (const float*)d_in[4];
    const float* wv = (const float*)d_in[5];
    const float* bv = (const float*)d_in[6];
    const float* wo = (const float*)d_in[7];
    const float* bo = (const float*)d_in[8];
    float* out = (float*)d_out;

    __half *xh, *wh, *q, *k, *v, *ctx;
    cudaGetSymbolAddress((void**)&xh,  g_xh);
    cudaGetSymbolAddress((void**)&wh,  g_wh);
    cudaGetSymbolAddress((void**)&q,   g_q);
    cudaGetSymbolAddress((void**)&k,   g_k);
    cudaGetSymbolAddress((void**)&v,   g_v);
    cudaGetSymbolAddress((void**)&ctx, g_ctx);

    constexpr int GSM = (int)sizeof(GemmSmem);
    cudaFuncSetAttribute(gemm_f16_kernel<0>,
                         cudaFuncAttributeMaxDynamicSharedMemorySize, GSM);
    cudaFuncSetAttribute(gemm_f16_kernel<1>,
                         cudaFuncAttributeMaxDynamicSharedMemorySize, GSM);

    // 1) fp16 conversion
    constexpr int NCONV = (int)(((size_t)MROWS * DM + 4 * (size_t)DM * DM) / 8);
    convert_kernel<<<NCONV / 256, 256>>>(x, wq, wk, wv, wo);

    // 2) merged QKV projection
    dim3 gqkv(DM / 128, MROWS / 128, 3);
    gemm_f16_kernel<1><<<gqkv, 256, GSM>>>(xh, wh, bq, bk, bv, q, k, v, nullptr);

    // 3) flash attention (128 q-rows per block)
    dim3 ga(S_LEN / 128, NH, BATCH);
    attn_f16_kernel<<<ga, 256>>>(q, k, v, ctx);

    // 4) output projection
    dim3 gg(DM / 128, MROWS / 128);
    gemm_f16_kernel<0><<<gg, 256, GSM>>>(ctx, wh + (size_t)3 * DM * DM,
                                         bo, nullptr, nullptr,
                                         nullptr, nullptr, nullptr, out);
}